// round 3
// baseline (speedup 1.0000x reference)
#include <cuda_runtime.h>

#define Bn   8
#define Tn   1024
#define Cn   768
#define Hn   12
#define HIDn 1536
#define Mn   16
#define Pn   4
#define PREn 20
#define TAn  1044
#define SLICES 16

// ---------------- scratch (device globals; no cudaMalloc allowed) ----------------
__device__ float g_q   [Bn*Tn*Cn];
__device__ float g_hbuf[Bn*Tn*HIDn];
__device__ float g_mem [Bn*Tn*Cn];
__device__ float g_pool[Bn*Mn*Cn];
__device__ float g_retr[Bn*Mn*Cn];
__device__ float g_xa  [Bn*TAn*Cn];
__device__ float g_hln [Bn*TAn*Cn];
__device__ float g_qkv [Bn*TAn*3*Cn];
__device__ float g_att [Bn*Hn*TAn*TAn];   // 104.6M floats (~418MB)
__device__ float g_y   [Bn*TAn*Cn];
__device__ float g_fc  [Bn*TAn*4*Cn];
__device__ float g_o   [Bn*Tn*Cn];
__device__ float g_key [Bn*Tn*Cn];
__device__ float g_val [Bn*Tn*Cn];
__device__ float g_pre [Bn*Tn*HIDn];
__device__ float g_hh  [Bn*Tn*HIDn];
__device__ float g_dpr [Bn*Tn*Cn];
__device__ float g_dhh [Bn*Tn*HIDn];
__device__ float g_p0  [SLICES*Bn*HIDn];
__device__ float g_p1  [SLICES*Bn*Cn];

// ---------------- generic strided batched GEMM with fused epilogues ----------------
// C[m,n] = sum_k A[m,k]*B[k,n]   (all strides explicit; batch offset = outer*b + inner*b2)
struct GP {
    const float* A; const float* Bm; float* O; float* O2;
    const float* bias; const float* aux; const float* aux2;
    int M, N, K, binner;
    long long sAm, sAk, bA, bA2;
    long long sBk, sBn, bB, bB2;
    long long sOm, sOn, bO, bO2;
    long long bBias;
    int mode, prefix;
    float scale;
};
// modes: 0=bias 1=silu(+pre->O2) 2=gelu 3=attn scale+mask 4=residual-add
//        5=dpred 6=silu-bwd(aux=pre) 7=momentum update (aux=mem, aux2=mom, O=nw, O2=nmom)

__global__ __launch_bounds__(256) void gemm_k(GP p) {
    __shared__ float As[8][128];
    __shared__ float Bs[8][128];
    int bz = blockIdx.z;
    int bo = bz / p.binner, bi = bz % p.binner;
    const float* Ap = p.A  + (long long)bo * p.bA + (long long)bi * p.bA2;
    const float* Bp = p.Bm + (long long)bo * p.bB + (long long)bi * p.bB2;
    int m0 = blockIdx.y * 128, n0 = blockIdx.x * 128;
    int tid = threadIdx.x, tx = tid & 15, ty = tid >> 4;
    float acc[8][8];
#pragma unroll
    for (int i = 0; i < 8; i++)
#pragma unroll
        for (int j = 0; j < 8; j++) acc[i][j] = 0.f;

    bool aRow  = (p.sAk == 1);
    bool bRowN = (p.sBn == 1);
    int nk = (p.K + 7) >> 3;
    for (int kt = 0; kt < nk; kt++) {
        int k0 = kt << 3;
        if (aRow) {
#pragma unroll
            for (int r = 0; r < 4; r++) {
                int lin = tid + r * 256;
                int km = lin & 7, mm = lin >> 3;
                int gm = m0 + mm, gk = k0 + km;
                As[km][mm] = (gm < p.M && gk < p.K) ? Ap[(long long)gm * p.sAm + gk] : 0.f;
            }
        } else {
#pragma unroll
            for (int r = 0; r < 4; r++) {
                int lin = tid + r * 256;
                int mm = lin & 127, km = lin >> 7;
                int gm = m0 + mm, gk = k0 + km;
                As[km][mm] = (gm < p.M && gk < p.K) ? Ap[gm + (long long)gk * p.sAk] : 0.f;
            }
        }
        if (bRowN) {
#pragma unroll
            for (int r = 0; r < 4; r++) {
                int lin = tid + r * 256;
                int nn = lin & 127, km = lin >> 7;
                int gn = n0 + nn, gk = k0 + km;
                Bs[km][nn] = (gn < p.N && gk < p.K) ? Bp[(long long)gk * p.sBk + gn] : 0.f;
            }
        } else {
#pragma unroll
            for (int r = 0; r < 4; r++) {
                int lin = tid + r * 256;
                int km = lin & 7, nn = lin >> 3;
                int gn = n0 + nn, gk = k0 + km;
                Bs[km][nn] = (gn < p.N && gk < p.K) ? Bp[gk + (long long)gn * p.sBn] : 0.f;
            }
        }
        __syncthreads();
#pragma unroll
        for (int kk = 0; kk < 8; kk++) {
            float ra[8], rb[8];
            *(float4*)(ra)     = *(const float4*)&As[kk][ty * 8];
            *(float4*)(ra + 4) = *(const float4*)&As[kk][ty * 8 + 4];
            *(float4*)(rb)     = *(const float4*)&Bs[kk][tx * 8];
            *(float4*)(rb + 4) = *(const float4*)&Bs[kk][tx * 8 + 4];
#pragma unroll
            for (int i = 0; i < 8; i++)
#pragma unroll
                for (int j = 0; j < 8; j++) acc[i][j] = fmaf(ra[i], rb[j], acc[i][j]);
        }
        __syncthreads();
    }

    long long offO = (long long)bo * p.bO + (long long)bi * p.bO2;
    long long offBias = p.bBias * bz;
#pragma unroll
    for (int i = 0; i < 8; i++) {
        int m = m0 + ty * 8 + i;
        if (m >= p.M) continue;
#pragma unroll
        for (int j = 0; j < 8; j++) {
            int n = n0 + tx * 8 + j;
            if (n >= p.N) continue;
            long long o = offO + (long long)m * p.sOm + (long long)n * p.sOn;
            float v = acc[i][j];
            float bsv = p.bias ? p.bias[offBias + n] : 0.f;
            switch (p.mode) {
                case 0: p.O[o] = v + bsv; break;
                case 1: { float z = v + bsv; if (p.O2) p.O2[o] = z;
                          float sg = 1.f / (1.f + __expf(-z)); p.O[o] = z * sg; } break;
                case 2: { float z = v + bsv; p.O[o] = 0.5f * z * (1.f + erff(z * 0.70710678118f)); } break;
                case 3: { float z = v * p.scale; if (m >= p.prefix && n > m) z = -1e30f; p.O[o] = z; } break;
                case 4: p.O[o] = p.aux[o] + v + bsv; break;
                case 5: p.O[o] = (v + bsv - p.aux[o]) * p.scale; break;
                case 6: { float z = p.aux[o]; float sg = 1.f / (1.f + __expf(-z));
                          p.O[o] = v * sg * (1.f + z * (1.f - sg)); } break;
                case 7: { float nm = 0.9f * p.aux2[o] + v; p.O2[o] = nm;
                          p.O[o] = 0.999f * p.aux[o] - 0.01f * nm; } break;
            }
        }
    }
}

// ---------------- elementwise / reduction kernels ----------------
__global__ void pool_k(const float* mem, float* pool) {
    int i = blockIdx.x * 256 + threadIdx.x;
    if (i >= Bn * Mn * Cn) return;
    int c = i % Cn;
    int r = i / Cn;
    int m = r % Mn;
    int b = r / Mn;
    const float* pp = mem + ((long long)b * Tn + m * (Tn / Mn)) * Cn + c;
    float s = 0.f;
#pragma unroll 8
    for (int j = 0; j < Tn / Mn; j++) s += pp[(long long)j * Cn];
    pool[i] = s * (1.f / (Tn / Mn));
}

__global__ void build_xa_k(const float* retr, const float* persist, const float* x, float* xa) {
    long long i = (long long)blockIdx.x * 256 + threadIdx.x;
    if (i >= (long long)Bn * TAn * Cn) return;
    int c = (int)(i % Cn);
    long long r = i / Cn;
    int t = (int)(r % TAn);
    int b = (int)(r / TAn);
    float v;
    if (t < Mn)        v = retr[((long long)b * Mn + t) * Cn + c];
    else if (t < PREn) v = persist[(long long)(t - Mn) * Cn + c];
    else               v = x[((long long)b * Tn + (t - PREn)) * Cn + c];
    xa[i] = v;
}

__global__ void ln_k(const float* x, float* o, const float* w, const float* bb) {
    long long row = blockIdx.x;
    const float* xr = x + row * Cn;
    float* orow = o + row * Cn;
    int t = threadIdx.x;
    __shared__ float s1[256], s2[256];
    float v0 = xr[t], v1 = xr[t + 256], v2 = xr[t + 512];
    s1[t] = v0 + v1 + v2;
    s2[t] = v0 * v0 + v1 * v1 + v2 * v2;
    __syncthreads();
    for (int st = 128; st > 0; st >>= 1) {
        if (t < st) { s1[t] += s1[t + st]; s2[t] += s2[t + st]; }
        __syncthreads();
    }
    float mean = s1[0] * (1.f / Cn);
    float var  = s2[0] * (1.f / Cn) - mean * mean;
    float rs = rsqrtf(var + 1e-5f);
    orow[t]       = (v0 - mean) * rs * w[t]       + bb[t];
    orow[t + 256] = (v1 - mean) * rs * w[t + 256] + bb[t + 256];
    orow[t + 512] = (v2 - mean) * rs * w[t + 512] + bb[t + 512];
}

__global__ void softmax_k(float* a) {
    long long row = blockIdx.x;
    float* r = a + row * TAn;
    int t = threadIdx.x;
    __shared__ float red[256];
    float mx = -1e30f;
    for (int c = t; c < TAn; c += 256) mx = fmaxf(mx, r[c]);
    red[t] = mx; __syncthreads();
    for (int st = 128; st > 0; st >>= 1) { if (t < st) red[t] = fmaxf(red[t], red[t + st]); __syncthreads(); }
    mx = red[0]; __syncthreads();
    float s = 0.f;
    for (int c = t; c < TAn; c += 256) { float e = __expf(r[c] - mx); r[c] = e; s += e; }
    red[t] = s; __syncthreads();
    for (int st = 128; st > 0; st >>= 1) { if (t < st) red[t] += red[t + st]; __syncthreads(); }
    float inv = 1.f / red[0];
    for (int c = t; c < TAn; c += 256) r[c] *= inv;
}

__global__ void copyout_k(const float* xa, float* go, float* dout) {
    long long i = (long long)blockIdx.x * 256 + threadIdx.x;
    if (i >= (long long)Bn * Tn * Cn) return;
    int c = (int)(i % Cn);
    long long r = i / Cn;
    int t = (int)(r % Tn);
    int b = (int)(r / Tn);
    float v = xa[((long long)b * TAn + PREn + t) * Cn + c];
    go[i] = v;
    dout[i] = v;
}

__global__ void colsum_part_k(const float* src, float* part, int cols) {
    int i = blockIdx.x * 256 + threadIdx.x;
    int total = SLICES * Bn * cols;
    if (i >= total) return;
    int s = i / (Bn * cols);
    int rem = i % (Bn * cols);
    int b = rem / cols, c = rem % cols;
    const float* p = src + ((long long)b * Tn + s * (Tn / SLICES)) * cols + c;
    float g = 0.f;
    for (int r = 0; r < Tn / SLICES; r++) g += p[(long long)r * cols];
    part[i] = g;
}

__global__ void colsum_fin_k(const float* part, const float* memb, const float* mom,
                             float* nb, float* nm, int n) {
    int i = blockIdx.x * 256 + threadIdx.x;
    if (i >= n) return;
    float g = 0.f;
    for (int s = 0; s < SLICES; s++) g += part[(long long)s * n + i];
    float m2 = 0.9f * mom[i] + g;
    nm[i] = m2;
    nb[i] = 0.999f * memb[i] - 0.01f * m2;
}

// ---------------- host ----------------
static void run_gemm(const float* A, long long sAm, long long sAk, long long bA, long long bA2,
                     const float* Bm, long long sBk, long long sBn, long long bB, long long bB2,
                     float* O, long long sOm, long long sOn, long long bO, long long bO2,
                     int M, int N, int K, int batch, int binner,
                     const float* bias, long long bBias, int mode,
                     float* O2, const float* aux, const float* aux2, float scale)
{
    GP p;
    p.A = A; p.Bm = Bm; p.O = O; p.O2 = O2; p.bias = bias; p.aux = aux; p.aux2 = aux2;
    p.M = M; p.N = N; p.K = K; p.binner = binner;
    p.sAm = sAm; p.sAk = sAk; p.bA = bA; p.bA2 = bA2;
    p.sBk = sBk; p.sBn = sBn; p.bB = bB; p.bB2 = bB2;
    p.sOm = sOm; p.sOn = sOn; p.bO = bO; p.bO2 = bO2;
    p.bBias = bBias; p.mode = mode; p.prefix = PREn; p.scale = scale;
    dim3 g((N + 127) / 128, (M + 127) / 128, batch);
    gemm_k<<<g, 256>>>(p);
}

extern "C" void kernel_launch(void* const* d_in, const int* in_sizes, int n_in,
                              void* d_out, int out_size) {
    const float* x           = (const float*)d_in[0];
    const float* persist     = (const float*)d_in[1];
    const float* ln1_w       = (const float*)d_in[2];
    const float* ln1_b       = (const float*)d_in[3];
    const float* ln2_w       = (const float*)d_in[4];
    const float* ln2_b       = (const float*)d_in[5];
    const float* attn_w      = (const float*)d_in[6];
    const float* attn_b      = (const float*)d_in[7];
    const float* attn_proj_w = (const float*)d_in[8];
    const float* attn_proj_b = (const float*)d_in[9];
    const float* fc_w        = (const float*)d_in[10];
    const float* fc_b        = (const float*)d_in[11];
    const float* mlp_proj_w  = (const float*)d_in[12];
    const float* mlp_proj_b  = (const float*)d_in[13];
    const float* q_w         = (const float*)d_in[14];
    const float* q_b         = (const float*)d_in[15];
    const float* k_w         = (const float*)d_in[16];
    const float* k_b         = (const float*)d_in[17];
    const float* v_w         = (const float*)d_in[18];
    const float* v_b         = (const float*)d_in[19];
    const float* o_w         = (const float*)d_in[20];
    const float* o_b         = (const float*)d_in[21];
    const float* mem_w0      = (const float*)d_in[22];
    const float* mem_b0      = (const float*)d_in[23];
    const float* mem_w1      = (const float*)d_in[24];
    const float* mem_b1      = (const float*)d_in[25];
    const float* mom_w0      = (const float*)d_in[26];
    const float* mom_b0      = (const float*)d_in[27];
    const float* mom_w1      = (const float*)d_in[28];
    const float* mom_b1      = (const float*)d_in[29];
    float* out = (float*)d_out;

    float *Q, *HB, *MEM, *POOL, *RETR, *XA, *HLN, *QKV, *ATT, *Y, *FC, *OUT, *KEY, *VAL,
          *PRE, *HH, *DPR, *DHH, *P0, *P1;
    cudaGetSymbolAddress((void**)&Q, g_q);
    cudaGetSymbolAddress((void**)&HB, g_hbuf);
    cudaGetSymbolAddress((void**)&MEM, g_mem);
    cudaGetSymbolAddress((void**)&POOL, g_pool);
    cudaGetSymbolAddress((void**)&RETR, g_retr);
    cudaGetSymbolAddress((void**)&XA, g_xa);
    cudaGetSymbolAddress((void**)&HLN, g_hln);
    cudaGetSymbolAddress((void**)&QKV, g_qkv);
    cudaGetSymbolAddress((void**)&ATT, g_att);
    cudaGetSymbolAddress((void**)&Y, g_y);
    cudaGetSymbolAddress((void**)&FC, g_fc);
    cudaGetSymbolAddress((void**)&OUT, g_o);
    cudaGetSymbolAddress((void**)&KEY, g_key);
    cudaGetSymbolAddress((void**)&VAL, g_val);
    cudaGetSymbolAddress((void**)&PRE, g_pre);
    cudaGetSymbolAddress((void**)&HH, g_hh);
    cudaGetSymbolAddress((void**)&DPR, g_dpr);
    cudaGetSymbolAddress((void**)&DHH, g_dhh);
    cudaGetSymbolAddress((void**)&P0, g_p0);
    cudaGetSymbolAddress((void**)&P1, g_p1);

    const long long TC   = (long long)Tn * Cn;
    const long long TH   = (long long)Tn * HIDn;
    const long long CH   = (long long)Cn * HIDn;   // w1 per-batch
    const long long HC   = (long long)HIDn * Cn;   // w0 per-batch
    const long long TAC  = (long long)TAn * Cn;
    const long long TA3C = (long long)TAn * 3 * Cn;
    const long long TATA = (long long)TAn * TAn;

    const long long o_nw0  = 6291456LL;
    const long long o_nb0  = 15728640LL;
    const long long o_nw1  = 15740928LL;
    const long long o_nb1  = 25178112LL;
    const long long o_nmw0 = 25184256LL;
    const long long o_nmb0 = 34621440LL;
    const long long o_nmw1 = 34633728LL;
    const long long o_nmb1 = 44070912LL;

    // 1. q = x @ q_w^T + q_b
    run_gemm(x, Cn, 1, 0, 0,  q_w, 1, Cn, 0, 0,  Q, Cn, 1, 0, 0,
             Bn * Tn, Cn, Cn, 1, 1, q_b, 0, 0, nullptr, nullptr, nullptr, 0.f);
    // 2. h = silu(q @ w0^T + b0)   (batched)
    run_gemm(Q, Cn, 1, TC, 0,  mem_w0, 1, Cn, HC, 0,  HB, HIDn, 1, TH, 0,
             Tn, HIDn, Cn, Bn, 1, mem_b0, HIDn, 1, nullptr, nullptr, nullptr, 0.f);
    // 3. mem = h @ w1^T + b1
    run_gemm(HB, HIDn, 1, TH, 0,  mem_w1, 1, HIDn, CH, 0,  MEM, Cn, 1, TC, 0,
             Tn, Cn, HIDn, Bn, 1, mem_b1, Cn, 0, nullptr, nullptr, nullptr, 0.f);
    // 4. pooled
    pool_k<<<(Bn * Mn * Cn + 255) / 256, 256>>>(MEM, POOL);
    // 5. retrieved = pooled @ o_w^T + o_b
    run_gemm(POOL, Cn, 1, 0, 0,  o_w, 1, Cn, 0, 0,  RETR, Cn, 1, 0, 0,
             Bn * Mn, Cn, Cn, 1, 1, o_b, 0, 0, nullptr, nullptr, nullptr, 0.f);
    // 6. xa = concat(retrieved, persist, x)
    build_xa_k<<<(int)(((long long)Bn * TAn * Cn + 255) / 256), 256>>>(RETR, persist, x, XA);
    // 7. ln1
    ln_k<<<Bn * TAn, 256>>>(XA, HLN, ln1_w, ln1_b);
    // 8. qkv
    run_gemm(HLN, Cn, 1, 0, 0,  attn_w, 1, Cn, 0, 0,  QKV, 3 * Cn, 1, 0, 0,
             Bn * TAn, 3 * Cn, Cn, 1, 1, attn_b, 0, 0, nullptr, nullptr, nullptr, 0.f);
    // 9. scores = scale * Q K^T with prefix-causal mask (batch B*H, inner H)
    run_gemm(QKV, 3 * Cn, 1, TA3C, 64,  QKV + Cn, 1, 3 * Cn, TA3C, 64,
             ATT, TAn, 1, (long long)Hn * TATA, TATA,
             TAn, TAn, 64, Bn * Hn, Hn, nullptr, 0, 3, nullptr, nullptr, nullptr, 0.125f);
    // 10. softmax
    softmax_k<<<Bn * Hn * TAn, 256>>>(ATT);
    // 11. y = att @ V
    run_gemm(ATT, TAn, 1, (long long)Hn * TATA, TATA,  QKV + 2 * Cn, 3 * Cn, 1, TA3C, 64,
             Y, Cn, 1, TAC, 64,
             TAn, 64, TAn, Bn * Hn, Hn, nullptr, 0, 0, nullptr, nullptr, nullptr, 0.f);
    // 12. xa += y @ attn_proj_w^T + b  (in-place residual)
    run_gemm(Y, Cn, 1, 0, 0,  attn_proj_w, 1, Cn, 0, 0,  XA, Cn, 1, 0, 0,
             Bn * TAn, Cn, Cn, 1, 1, attn_proj_b, 0, 4, nullptr, XA, nullptr, 0.f);
    // 13. ln2
    ln_k<<<Bn * TAn, 256>>>(XA, HLN, ln2_w, ln2_b);
    // 14. fc = gelu(h2 @ fc_w^T + fc_b)
    run_gemm(HLN, Cn, 1, 0, 0,  fc_w, 1, Cn, 0, 0,  FC, 4 * Cn, 1, 0, 0,
             Bn * TAn, 4 * Cn, Cn, 1, 1, fc_b, 0, 2, nullptr, nullptr, nullptr, 0.f);
    // 15. xa += fc @ mlp_proj_w^T + b
    run_gemm(FC, 4 * Cn, 1, 0, 0,  mlp_proj_w, 1, 4 * Cn, 0, 0,  XA, Cn, 1, 0, 0,
             Bn * TAn, Cn, 4 * Cn, 1, 1, mlp_proj_b, 0, 4, nullptr, XA, nullptr, 0.f);
    // 16. out = xa[:, prefix:, :]  (to scratch + d_out)
    copyout_k<<<(int)(((long long)Bn * Tn * Cn + 255) / 256), 256>>>(XA, OUT, out);
    // 17. keys / vals
    run_gemm(OUT, Cn, 1, 0, 0,  k_w, 1, Cn, 0, 0,  KEY, Cn, 1, 0, 0,
             Bn * Tn, Cn, Cn, 1, 1, k_b, 0, 0, nullptr, nullptr, nullptr, 0.f);
    run_gemm(OUT, Cn, 1, 0, 0,  v_w, 1, Cn, 0, 0,  VAL, Cn, 1, 0, 0,
             Bn * Tn, Cn, Cn, 1, 1, v_b, 0, 0, nullptr, nullptr, nullptr, 0.f);
    // 18. pre = keys @ w0^T + b0 ; hh = silu(pre)
    run_gemm(KEY, Cn, 1, TC, 0,  mem_w0, 1, Cn, HC, 0,  HH, HIDn, 1, TH, 0,
             Tn, HIDn, Cn, Bn, 1, mem_b0, HIDn, 1, PRE, nullptr, nullptr, 0.f);
    // 19. dpred = 2*(hh @ w1^T + b1 - vals)/(T*C)
    run_gemm(HH, HIDn, 1, TH, 0,  mem_w1, 1, HIDn, CH, 0,  DPR, Cn, 1, TC, 0,
             Tn, Cn, HIDn, Bn, 1, mem_b1, Cn, 5, nullptr, VAL, nullptr,
             2.f / (float)(Tn * Cn));
    // 20. g_w1 = dpred^T @ hh ; momentum update -> nw1, nmom_w1
    run_gemm(DPR, 1, Cn, TC, 0,  HH, HIDn, 1, TH, 0,  out + o_nw1, HIDn, 1, CH, 0,
             Cn, HIDn, Tn, Bn, 1, nullptr, 0, 7, out + o_nmw1, mem_w1, mom_w1, 0.f);
    // 21. dh_pre = (dpred @ w1) * silu'(pre)
    run_gemm(DPR, Cn, 1, TC, 0,  mem_w1, HIDn, 1, CH, 0,  DHH, HIDn, 1, TH, 0,
             Tn, HIDn, Cn, Bn, 1, nullptr, 0, 6, nullptr, PRE, nullptr, 0.f);
    // 22. g_w0 = dh_pre^T @ keys ; update -> nw0, nmom_w0
    run_gemm(DHH, 1, HIDn, TH, 0,  KEY, Cn, 1, TC, 0,  out + o_nw0, Cn, 1, HC, 0,
             HIDn, Cn, Tn, Bn, 1, nullptr, 0, 7, out + o_nmw0, mem_w0, mom_w0, 0.f);
    // 23. bias grads + updates
    colsum_part_k<<<(SLICES * Bn * Cn + 255) / 256, 256>>>(DPR, P1, Cn);
    colsum_fin_k<<<(Bn * Cn + 255) / 256, 256>>>(P1, mem_b1, mom_b1,
                                                 out + o_nb1, out + o_nmb1, Bn * Cn);
    colsum_part_k<<<(SLICES * Bn * HIDn + 255) / 256, 256>>>(DHH, P0, HIDn);
    colsum_fin_k<<<(Bn * HIDn + 255) / 256, 256>>>(P0, mem_b0, mom_b0,
                                                   out + o_nb0, out + o_nmb0, Bn * HIDn);
    (void)in_sizes; (void)n_in; (void)out_size;
}

// round 5
// speedup vs baseline: 2.0799x; 2.0799x over previous
#include <cuda_runtime.h>

#define Bn   8
#define Tn   1024
#define Cn   768
#define Hn   12
#define HIDn 1536
#define Mn   16
#define Pn   4
#define PREn 20
#define TAn  1044
#define SLICES 16

// ---------------- scratch (device globals; no cudaMalloc allowed) ----------------
__device__ float g_q   [Bn*Tn*Cn];
__device__ float g_hbuf[Bn*Tn*HIDn];
__device__ float g_mem [Bn*Tn*Cn];
__device__ float g_pool[Bn*Mn*Cn];
__device__ float g_retr[Bn*Mn*Cn];
__device__ float g_xa  [Bn*TAn*Cn];
__device__ float g_hln [Bn*TAn*Cn];
__device__ float g_qkv [Bn*TAn*3*Cn];
__device__ float g_att [Bn*Hn*TAn*TAn];   // ~418MB
__device__ float g_y   [Bn*TAn*Cn];
__device__ float g_fc  [Bn*TAn*4*Cn];
__device__ float g_o   [Bn*Tn*Cn];
__device__ float g_key [Bn*Tn*Cn];
__device__ float g_val [Bn*Tn*Cn];
__device__ float g_pre [Bn*Tn*HIDn];
__device__ float g_hh  [Bn*Tn*HIDn];
__device__ float g_dpr [Bn*Tn*Cn];
__device__ float g_dhh [Bn*Tn*HIDn];
__device__ float g_p0  [SLICES*Bn*HIDn];
__device__ float g_p1  [SLICES*Bn*Cn];

// ---------------- generic strided batched GEMM params ----------------
struct GP {
    const float* A; const float* Bm; float* O; float* O2;
    const float* bias; const float* aux; const float* aux2;
    int M, N, K, binner;
    long long sAm, sAk, bA, bA2;
    long long sBk, sBn, bB, bB2;
    long long sOm, sOn, bO, bO2;
    long long bBias;
    int mode, prefix;
    float scale;
};
// modes: 0=bias 1=silu(+pre->O2) 2=gelu 3=attn scale+mask 4=residual-add
//        5=dpred 6=silu-bwd(aux=pre) 7=momentum update (aux=mem, aux2=mom, O=nw, O2=nmom)

__device__ __forceinline__ unsigned f2tf(float x) {
    unsigned r;
    asm("cvt.rna.tf32.f32 %0, %1;" : "=r"(r) : "f"(x));
    return r;
}

__device__ __forceinline__ void mma_tf32(float* c, const unsigned* a, const unsigned* b) {
    asm volatile(
        "mma.sync.aligned.m16n8k8.row.col.f32.tf32.tf32.f32 "
        "{%0,%1,%2,%3}, {%4,%5,%6,%7}, {%8,%9}, {%0,%1,%2,%3};\n"
        : "+f"(c[0]), "+f"(c[1]), "+f"(c[2]), "+f"(c[3])
        : "r"(a[0]), "r"(a[1]), "r"(a[2]), "r"(a[3]), "r"(b[0]), "r"(b[1]));
}

__device__ __forceinline__ void epi_write(const GP& p, int m, int n, float v,
                                          long long offO, long long offBias) {
    if (m >= p.M || n >= p.N) return;
    long long o = offO + (long long)m * p.sOm + (long long)n * p.sOn;
    float bsv = p.bias ? p.bias[offBias + n] : 0.f;
    switch (p.mode) {
        case 0: p.O[o] = v + bsv; break;
        case 1: { float z = v + bsv; if (p.O2) p.O2[o] = z;
                  float sg = 1.f / (1.f + __expf(-z)); p.O[o] = z * sg; } break;
        case 2: { float z = v + bsv; p.O[o] = 0.5f * z * (1.f + erff(z * 0.70710678118f)); } break;
        case 3: { float z = v * p.scale; if (m >= p.prefix && n > m) z = -1e30f; p.O[o] = z; } break;
        case 4: p.O[o] = p.aux[o] + v + bsv; break;
        case 5: p.O[o] = (v + bsv - p.aux[o]) * p.scale; break;
        case 6: { float z = p.aux[o]; float sg = 1.f / (1.f + __expf(-z));
                  p.O[o] = v * sg * (1.f + z * (1.f - sg)); } break;
        case 7: { float nm = 0.9f * p.aux2[o] + v; p.O2[o] = nm;
                  p.O[o] = 0.999f * p.aux[o] - 0.01f * nm; } break;
    }
}

// ---------------- tf32 tensor-core GEMM: 128x128 block, k-tile 16, 8 warps ----------------
__global__ __launch_bounds__(256) void gemm_tc(GP p) {
    __shared__ float As[16][132];
    __shared__ float Bs[16][132];
    int bz = blockIdx.z;
    int bo = bz / p.binner, bi = bz % p.binner;
    const float* Ap = p.A  + (long long)bo * p.bA + (long long)bi * p.bA2;
    const float* Bp = p.Bm + (long long)bo * p.bB + (long long)bi * p.bB2;
    int m0 = blockIdx.y * 128, n0 = blockIdx.x * 128;
    int tid = threadIdx.x;
    int warp = tid >> 5, lane = tid & 31;
    int wm = warp & 1, wn = warp >> 1;      // warp tile: 64 (m) x 32 (n)
    int lq = lane >> 2, lr = lane & 3;

    float acc[4][4][4];
#pragma unroll
    for (int i = 0; i < 4; i++)
#pragma unroll
        for (int j = 0; j < 4; j++)
#pragma unroll
            for (int r = 0; r < 4; r++) acc[i][j][r] = 0.f;

    bool aK = (p.sAk == 1);     // A contiguous along k
    bool bN = (p.sBn == 1);     // B contiguous along n
    int nk = (p.K + 15) >> 4;

    for (int kt = 0; kt < nk; kt++) {
        int k0 = kt << 4;
        // ---- load A tile (16 x 128) ----
        if (aK) {
#pragma unroll
            for (int r = 0; r < 8; r++) {
                int lin = tid + r * 256;
                int kk = lin & 15, mm = lin >> 4;
                int gm = m0 + mm, gk = k0 + kk;
                As[kk][mm] = (gm < p.M && gk < p.K)
                    ? Ap[(long long)gm * p.sAm + (long long)gk * p.sAk] : 0.f;
            }
        } else {
#pragma unroll
            for (int r = 0; r < 8; r++) {
                int lin = tid + r * 256;
                int mm = lin & 127, kk = lin >> 7;
                int gm = m0 + mm, gk = k0 + kk;
                As[kk][mm] = (gm < p.M && gk < p.K)
                    ? Ap[(long long)gm * p.sAm + (long long)gk * p.sAk] : 0.f;
            }
        }
        // ---- load B tile (16 x 128) ----
        if (bN) {
#pragma unroll
            for (int r = 0; r < 8; r++) {
                int lin = tid + r * 256;
                int nn = lin & 127, kk = lin >> 7;
                int gn = n0 + nn, gk = k0 + kk;
                Bs[kk][nn] = (gn < p.N && gk < p.K)
                    ? Bp[(long long)gk * p.sBk + (long long)gn * p.sBn] : 0.f;
            }
        } else {
#pragma unroll
            for (int r = 0; r < 8; r++) {
                int lin = tid + r * 256;
                int kk = lin & 15, nn = lin >> 4;
                int gn = n0 + nn, gk = k0 + kk;
                Bs[kk][nn] = (gn < p.N && gk < p.K)
                    ? Bp[(long long)gk * p.sBk + (long long)gn * p.sBn] : 0.f;
            }
        }
        __syncthreads();

#pragma unroll
        for (int ks = 0; ks < 16; ks += 8) {
            unsigned af[4][4], bf[4][2];
#pragma unroll
            for (int mf = 0; mf < 4; mf++) {
                int cm = wm * 64 + mf * 16 + lq;
                af[mf][0] = f2tf(As[ks + lr][cm]);
                af[mf][1] = f2tf(As[ks + lr][cm + 8]);
                af[mf][2] = f2tf(As[ks + lr + 4][cm]);
                af[mf][3] = f2tf(As[ks + lr + 4][cm + 8]);
            }
#pragma unroll
            for (int nf = 0; nf < 4; nf++) {
                int cn = wn * 32 + nf * 8 + lq;
                bf[nf][0] = f2tf(Bs[ks + lr][cn]);
                bf[nf][1] = f2tf(Bs[ks + lr + 4][cn]);
            }
#pragma unroll
            for (int mf = 0; mf < 4; mf++)
#pragma unroll
                for (int nf = 0; nf < 4; nf++)
                    mma_tf32(acc[mf][nf], af[mf], bf[nf]);
        }
        __syncthreads();
    }

    long long offO = (long long)bo * p.bO + (long long)bi * p.bO2;
    long long offBias = p.bBias * bz;
#pragma unroll
    for (int mf = 0; mf < 4; mf++) {
        int row = m0 + wm * 64 + mf * 16 + lq;
#pragma unroll
        for (int nf = 0; nf < 4; nf++) {
            int col = n0 + wn * 32 + nf * 8 + lr * 2;
            epi_write(p, row,     col,     acc[mf][nf][0], offO, offBias);
            epi_write(p, row,     col + 1, acc[mf][nf][1], offO, offBias);
            epi_write(p, row + 8, col,     acc[mf][nf][2], offO, offBias);
            epi_write(p, row + 8, col + 1, acc[mf][nf][3], offO, offBias);
        }
    }
}

// ---------------- elementwise / reduction kernels ----------------
__global__ void pool_k(const float* mem, float* pool) {
    int i = blockIdx.x * 256 + threadIdx.x;
    if (i >= Bn * Mn * Cn) return;
    int c = i % Cn;
    int r = i / Cn;
    int m = r % Mn;
    int b = r / Mn;
    const float* pp = mem + ((long long)b * Tn + m * (Tn / Mn)) * Cn + c;
    float s = 0.f;
#pragma unroll 8
    for (int j = 0; j < Tn / Mn; j++) s += pp[(long long)j * Cn];
    pool[i] = s * (1.f / (Tn / Mn));
}

__global__ void build_xa_k(const float* retr, const float* persist, const float* x, float* xa) {
    long long i = (long long)blockIdx.x * 256 + threadIdx.x;
    if (i >= (long long)Bn * TAn * Cn) return;
    int c = (int)(i % Cn);
    long long r = i / Cn;
    int t = (int)(r % TAn);
    int b = (int)(r / TAn);
    float v;
    if (t < Mn)        v = retr[((long long)b * Mn + t) * Cn + c];
    else if (t < PREn) v = persist[(long long)(t - Mn) * Cn + c];
    else               v = x[((long long)b * Tn + (t - PREn)) * Cn + c];
    xa[i] = v;
}

__global__ void ln_k(const float* x, float* o, const float* w, const float* bb) {
    long long row = blockIdx.x;
    const float* xr = x + row * Cn;
    float* orow = o + row * Cn;
    int t = threadIdx.x;
    __shared__ float s1[256], s2[256];
    float v0 = xr[t], v1 = xr[t + 256], v2 = xr[t + 512];
    s1[t] = v0 + v1 + v2;
    s2[t] = v0 * v0 + v1 * v1 + v2 * v2;
    __syncthreads();
    for (int st = 128; st > 0; st >>= 1) {
        if (t < st) { s1[t] += s1[t + st]; s2[t] += s2[t + st]; }
        __syncthreads();
    }
    float mean = s1[0] * (1.f / Cn);
    float var  = s2[0] * (1.f / Cn) - mean * mean;
    float rs = rsqrtf(var + 1e-5f);
    orow[t]       = (v0 - mean) * rs * w[t]       + bb[t];
    orow[t + 256] = (v1 - mean) * rs * w[t + 256] + bb[t + 256];
    orow[t + 512] = (v2 - mean) * rs * w[t + 512] + bb[t + 512];
}

__global__ void softmax_k(float* a) {
    long long row = blockIdx.x;
    float* r = a + row * TAn;
    int t = threadIdx.x;
    __shared__ float red[256];
    float mx = -1e30f;
    for (int c = t; c < TAn; c += 256) mx = fmaxf(mx, r[c]);
    red[t] = mx; __syncthreads();
    for (int st = 128; st > 0; st >>= 1) { if (t < st) red[t] = fmaxf(red[t], red[t + st]); __syncthreads(); }
    mx = red[0]; __syncthreads();
    float s = 0.f;
    for (int c = t; c < TAn; c += 256) { float e = __expf(r[c] - mx); r[c] = e; s += e; }
    red[t] = s; __syncthreads();
    for (int st = 128; st > 0; st >>= 1) { if (t < st) red[t] += red[t + st]; __syncthreads(); }
    float inv = 1.f / red[0];
    for (int c = t; c < TAn; c += 256) r[c] *= inv;
}

__global__ void copyout_k(const float* xa, float* go, float* dout) {
    long long i = (long long)blockIdx.x * 256 + threadIdx.x;
    if (i >= (long long)Bn * Tn * Cn) return;
    int c = (int)(i % Cn);
    long long r = i / Cn;
    int t = (int)(r % Tn);
    int b = (int)(r / Tn);
    float v = xa[((long long)b * TAn + PREn + t) * Cn + c];
    go[i] = v;
    dout[i] = v;
}

__global__ void colsum_part_k(const float* src, float* part, int cols) {
    int i = blockIdx.x * 256 + threadIdx.x;
    int total = SLICES * Bn * cols;
    if (i >= total) return;
    int s = i / (Bn * cols);
    int rem = i % (Bn * cols);
    int b = rem / cols, c = rem % cols;
    const float* p = src + ((long long)b * Tn + s * (Tn / SLICES)) * cols + c;
    float g = 0.f;
    for (int r = 0; r < Tn / SLICES; r++) g += p[(long long)r * cols];
    part[i] = g;
}

__global__ void colsum_fin_k(const float* part, const float* memb, const float* mom,
                             float* nb, float* nm, int n) {
    int i = blockIdx.x * 256 + threadIdx.x;
    if (i >= n) return;
    float g = 0.f;
    for (int s = 0; s < SLICES; s++) g += part[(long long)s * n + i];
    float m2 = 0.9f * mom[i] + g;
    nm[i] = m2;
    nb[i] = 0.999f * memb[i] - 0.01f * m2;
}

// ---------------- host ----------------
static void run_gemm(const float* A, long long sAm, long long sAk, long long bA, long long bA2,
                     const float* Bm, long long sBk, long long sBn, long long bB, long long bB2,
                     float* O, long long sOm, long long sOn, long long bO, long long bO2,
                     int M, int N, int K, int batch, int binner,
                     const float* bias, long long bBias, int mode,
                     float* O2, const float* aux, const float* aux2, float scale)
{
    GP p;
    p.A = A; p.Bm = Bm; p.O = O; p.O2 = O2; p.bias = bias; p.aux = aux; p.aux2 = aux2;
    p.M = M; p.N = N; p.K = K; p.binner = binner;
    p.sAm = sAm; p.sAk = sAk; p.bA = bA; p.bA2 = bA2;
    p.sBk = sBk; p.sBn = sBn; p.bB = bB; p.bB2 = bB2;
    p.sOm = sOm; p.sOn = sOn; p.bO = bO; p.bO2 = bO2;
    p.bBias = bBias; p.mode = mode; p.prefix = PREn; p.scale = scale;
    dim3 g((N + 127) / 128, (M + 127) / 128, batch);
    gemm_tc<<<g, 256>>>(p);
}

extern "C" void kernel_launch(void* const* d_in, const int* in_sizes, int n_in,
                              void* d_out, int out_size) {
    const float* x           = (const float*)d_in[0];
    const float* persist     = (const float*)d_in[1];
    const float* ln1_w       = (const float*)d_in[2];
    const float* ln1_b       = (const float*)d_in[3];
    const float* ln2_w       = (const float*)d_in[4];
    const float* ln2_b       = (const float*)d_in[5];
    const float* attn_w      = (const float*)d_in[6];
    const float* attn_b      = (const float*)d_in[7];
    const float* attn_proj_w = (const float*)d_in[8];
    const float* attn_proj_b = (const float*)d_in[9];
    const float* fc_w        = (const float*)d_in[10];
    const float* fc_b        = (const float*)d_in[11];
    const float* mlp_proj_w  = (const float*)d_in[12];
    const float* mlp_proj_b  = (const float*)d_in[13];
    const float* q_w         = (const float*)d_in[14];
    const float* q_b         = (const float*)d_in[15];
    const float* k_w         = (const float*)d_in[16];
    const float* k_b         = (const float*)d_in[17];
    const float* v_w         = (const float*)d_in[18];
    const float* v_b         = (const float*)d_in[19];
    const float* o_w         = (const float*)d_in[20];
    const float* o_b         = (const float*)d_in[21];
    const float* mem_w0      = (const float*)d_in[22];
    const float* mem_b0      = (const float*)d_in[23];
    const float* mem_w1      = (const float*)d_in[24];
    const float* mem_b1      = (const float*)d_in[25];
    const float* mom_w0      = (const float*)d_in[26];
    const float* mom_b0      = (const float*)d_in[27];
    const float* mom_w1      = (const float*)d_in[28];
    const float* mom_b1      = (const float*)d_in[29];
    float* out = (float*)d_out;

    float *Q, *HB, *MEM, *POOL, *RETR, *XA, *HLN, *QKV, *ATT, *Y, *FC, *OUT, *KEY, *VAL,
          *PRE, *HH, *DPR, *DHH, *P0, *P1;
    cudaGetSymbolAddress((void**)&Q, g_q);
    cudaGetSymbolAddress((void**)&HB, g_hbuf);
    cudaGetSymbolAddress((void**)&MEM, g_mem);
    cudaGetSymbolAddress((void**)&POOL, g_pool);
    cudaGetSymbolAddress((void**)&RETR, g_retr);
    cudaGetSymbolAddress((void**)&XA, g_xa);
    cudaGetSymbolAddress((void**)&HLN, g_hln);
    cudaGetSymbolAddress((void**)&QKV, g_qkv);
    cudaGetSymbolAddress((void**)&ATT, g_att);
    cudaGetSymbolAddress((void**)&Y, g_y);
    cudaGetSymbolAddress((void**)&FC, g_fc);
    cudaGetSymbolAddress((void**)&OUT, g_o);
    cudaGetSymbolAddress((void**)&KEY, g_key);
    cudaGetSymbolAddress((void**)&VAL, g_val);
    cudaGetSymbolAddress((void**)&PRE, g_pre);
    cudaGetSymbolAddress((void**)&HH, g_hh);
    cudaGetSymbolAddress((void**)&DPR, g_dpr);
    cudaGetSymbolAddress((void**)&DHH, g_dhh);
    cudaGetSymbolAddress((void**)&P0, g_p0);
    cudaGetSymbolAddress((void**)&P1, g_p1);

    const long long TC   = (long long)Tn * Cn;
    const long long TH   = (long long)Tn * HIDn;
    const long long CH   = (long long)Cn * HIDn;
    const long long HC   = (long long)HIDn * Cn;
    const long long TAC  = (long long)TAn * Cn;
    const long long TA3C = (long long)TAn * 3 * Cn;
    const long long TATA = (long long)TAn * TAn;

    const long long o_nw0  = 6291456LL;
    const long long o_nb0  = 15728640LL;
    const long long o_nw1  = 15740928LL;
    const long long o_nb1  = 25178112LL;
    const long long o_nmw0 = 25184256LL;
    const long long o_nmb0 = 34621440LL;
    const long long o_nmw1 = 34633728LL;
    const long long o_nmb1 = 44070912LL;

    // 1. q = x @ q_w^T + q_b
    run_gemm(x, Cn, 1, 0, 0,  q_w, 1, Cn, 0, 0,  Q, Cn, 1, 0, 0,
             Bn * Tn, Cn, Cn, 1, 1, q_b, 0, 0, nullptr, nullptr, nullptr, 0.f);
    // 2. h = silu(q @ w0^T + b0)
    run_gemm(Q, Cn, 1, TC, 0,  mem_w0, 1, Cn, HC, 0,  HB, HIDn, 1, TH, 0,
             Tn, HIDn, Cn, Bn, 1, mem_b0, HIDn, 1, nullptr, nullptr, nullptr, 0.f);
    // 3. mem = h @ w1^T + b1
    run_gemm(HB, HIDn, 1, TH, 0,  mem_w1, 1, HIDn, CH, 0,  MEM, Cn, 1, TC, 0,
             Tn, Cn, HIDn, Bn, 1, mem_b1, Cn, 0, nullptr, nullptr, nullptr, 0.f);
    // 4. pooled
    pool_k<<<(Bn * Mn * Cn + 255) / 256, 256>>>(MEM, POOL);
    // 5. retrieved = pooled @ o_w^T + o_b
    run_gemm(POOL, Cn, 1, 0, 0,  o_w, 1, Cn, 0, 0,  RETR, Cn, 1, 0, 0,
             Bn * Mn, Cn, Cn, 1, 1, o_b, 0, 0, nullptr, nullptr, nullptr, 0.f);
    // 6. xa = concat(retrieved, persist, x)
    build_xa_k<<<(int)(((long long)Bn * TAn * Cn + 255) / 256), 256>>>(RETR, persist, x, XA);
    // 7. ln1
    ln_k<<<Bn * TAn, 256>>>(XA, HLN, ln1_w, ln1_b);
    // 8. qkv
    run_gemm(HLN, Cn, 1, 0, 0,  attn_w, 1, Cn, 0, 0,  QKV, 3 * Cn, 1, 0, 0,
             Bn * TAn, 3 * Cn, Cn, 1, 1, attn_b, 0, 0, nullptr, nullptr, nullptr, 0.f);
    // 9. scores = scale * Q K^T with prefix-causal mask
    run_gemm(QKV, 3 * Cn, 1, TA3C, 64,  QKV + Cn, 1, 3 * Cn, TA3C, 64,
             ATT, TAn, 1, (long long)Hn * TATA, TATA,
             TAn, TAn, 64, Bn * Hn, Hn, nullptr, 0, 3, nullptr, nullptr, nullptr, 0.125f);
    // 10. softmax
    softmax_k<<<Bn * Hn * TAn, 256>>>(ATT);
    // 11. y = att @ V
    run_gemm(ATT, TAn, 1, (long long)Hn * TATA, TATA,  QKV + 2 * Cn, 3 * Cn, 1, TA3C, 64,
             Y, Cn, 1, TAC, 64,
             TAn, 64, TAn, Bn * Hn, Hn, nullptr, 0, 0, nullptr, nullptr, nullptr, 0.f);
    // 12. xa += y @ attn_proj_w^T + b
    run_gemm(Y, Cn, 1, 0, 0,  attn_proj_w, 1, Cn, 0, 0,  XA, Cn, 1, 0, 0,
             Bn * TAn, Cn, Cn, 1, 1, attn_proj_b, 0, 4, nullptr, XA, nullptr, 0.f);
    // 13. ln2
    ln_k<<<Bn * TAn, 256>>>(XA, HLN, ln2_w, ln2_b);
    // 14. fc = gelu(h2 @ fc_w^T + fc_b)
    run_gemm(HLN, Cn, 1, 0, 0,  fc_w, 1, Cn, 0, 0,  FC, 4 * Cn, 1, 0, 0,
             Bn * TAn, 4 * Cn, Cn, 1, 1, fc_b, 0, 2, nullptr, nullptr, nullptr, 0.f);
    // 15. xa += fc @ mlp_proj_w^T + b
    run_gemm(FC, 4 * Cn, 1, 0, 0,  mlp_proj_w, 1, 4 * Cn, 0, 0,  XA, Cn, 1, 0, 0,
             Bn * TAn, Cn, 4 * Cn, 1, 1, mlp_proj_b, 0, 4, nullptr, XA, nullptr, 0.f);
    // 16. out slice
    copyout_k<<<(int)(((long long)Bn * Tn * Cn + 255) / 256), 256>>>(XA, OUT, out);
    // 17. keys / vals
    run_gemm(OUT, Cn, 1, 0, 0,  k_w, 1, Cn, 0, 0,  KEY, Cn, 1, 0, 0,
             Bn * Tn, Cn, Cn, 1, 1, k_b, 0, 0, nullptr, nullptr, nullptr, 0.f);
    run_gemm(OUT, Cn, 1, 0, 0,  v_w, 1, Cn, 0, 0,  VAL, Cn, 1, 0, 0,
             Bn * Tn, Cn, Cn, 1, 1, v_b, 0, 0, nullptr, nullptr, nullptr, 0.f);
    // 18. pre = keys @ w0^T + b0 ; hh = silu(pre)
    run_gemm(KEY, Cn, 1, TC, 0,  mem_w0, 1, Cn, HC, 0,  HH, HIDn, 1, TH, 0,
             Tn, HIDn, Cn, Bn, 1, mem_b0, HIDn, 1, PRE, nullptr, nullptr, 0.f);
    // 19. dpred = 2*(hh @ w1^T + b1 - vals)/(T*C)
    run_gemm(HH, HIDn, 1, TH, 0,  mem_w1, 1, HIDn, CH, 0,  DPR, Cn, 1, TC, 0,
             Tn, Cn, HIDn, Bn, 1, mem_b1, Cn, 5, nullptr, VAL, nullptr,
             2.f / (float)(Tn * Cn));
    // 20. g_w1 = dpred^T @ hh ; update
    run_gemm(DPR, 1, Cn, TC, 0,  HH, HIDn, 1, TH, 0,  out + o_nw1, HIDn, 1, CH, 0,
             Cn, HIDn, Tn, Bn, 1, nullptr, 0, 7, out + o_nmw1, mem_w1, mom_w1, 0.f);
    // 21. dh_pre = (dpred @ w1) * silu'(pre)
    run_gemm(DPR, Cn, 1, TC, 0,  mem_w1, HIDn, 1, CH, 0,  DHH, HIDn, 1, TH, 0,
             Tn, HIDn, Cn, Bn, 1, nullptr, 0, 6, nullptr, PRE, nullptr, 0.f);
    // 22. g_w0 = dh_pre^T @ keys ; update
    run_gemm(DHH, 1, HIDn, TH, 0,  KEY, Cn, 1, TC, 0,  out + o_nw0, Cn, 1, HC, 0,
             HIDn, Cn, Tn, Bn, 1, nullptr, 0, 7, out + o_nmw0, mem_w0, mom_w0, 0.f);
    // 23. bias grads + updates
    colsum_part_k<<<(SLICES * Bn * Cn + 255) / 256, 256>>>(DPR, P1, Cn);
    colsum_fin_k<<<(Bn * Cn + 255) / 256, 256>>>(P1, mem_b1, mom_b1,
                                                 out + o_nb1, out + o_nmb1, Bn * Cn);
    colsum_part_k<<<(SLICES * Bn * HIDn + 255) / 256, 256>>>(DHH, P0, HIDn);
    colsum_fin_k<<<(Bn * HIDn + 255) / 256, 256>>>(P0, mem_b0, mom_b0,
                                                   out + o_nb0, out + o_nmb0, Bn * HIDn);
    (void)in_sizes; (void)n_in; (void)out_size;
}

// round 8
// speedup vs baseline: 4.2870x; 2.0612x over previous
#include <cuda_runtime.h>

#define Bn   8
#define Tn   1024
#define Cn   768
#define Hn   12
#define HIDn 1536
#define Mn   16
#define Pn   4
#define PREn 20
#define TAn  1044
#define SLICES 16

// ---------------- scratch (device globals; no cudaMalloc allowed) ----------------
__device__ float g_q   [Bn*Tn*Cn];
__device__ float g_hbuf[Bn*Tn*HIDn];
__device__ float g_mem [Bn*Tn*Cn];
__device__ float g_pool[Bn*Mn*Cn];
__device__ float g_retr[Bn*Mn*Cn];
__device__ float g_xa  [Bn*TAn*Cn];
__device__ float g_hln [Bn*TAn*Cn];
__device__ float g_qkv [Bn*TAn*3*Cn];
__device__ float g_att [Bn*Hn*TAn*TAn];   // ~418MB
__device__ float g_y   [Bn*TAn*Cn];
__device__ float g_fc  [Bn*TAn*4*Cn];
__device__ float g_o   [Bn*Tn*Cn];
__device__ float g_key [Bn*Tn*Cn];
__device__ float g_val [Bn*Tn*Cn];
__device__ float g_pre [Bn*Tn*HIDn];
__device__ float g_hh  [Bn*Tn*HIDn];
__device__ float g_dpr [Bn*Tn*Cn];
__device__ float g_dhh [Bn*Tn*HIDn];
__device__ float g_p0  [SLICES*Bn*HIDn];
__device__ float g_p1  [SLICES*Bn*Cn];

// ---------------- generic strided batched GEMM params ----------------
struct GP {
    const float* A; const float* Bm; float* O; float* O2;
    const float* bias; const float* aux; const float* aux2;
    int M, N, K, binner;
    long long sAm, sAk, bA, bA2;
    long long sBk, sBn, bB, bB2;
    long long sOm, sOn, bO, bO2;
    long long bBias;
    int mode, prefix;
    float scale;
};
// modes: 0=bias 1=silu(+pre->O2) 2=gelu 3=attn scale+mask 4=residual-add
//        5=dpred 6=silu-bwd(aux=pre) 7=momentum update (aux=mem, aux2=mom, O=nw, O2=nmom)

__device__ __forceinline__ unsigned f2tf(float x) {
    unsigned r;
    asm("cvt.rna.tf32.f32 %0, %1;" : "=r"(r) : "f"(x));
    return r;
}

__device__ __forceinline__ void mma_tf32(float* c, const unsigned* a, const unsigned* b) {
    asm volatile(
        "mma.sync.aligned.m16n8k8.row.col.f32.tf32.tf32.f32 "
        "{%0,%1,%2,%3}, {%4,%5,%6,%7}, {%8,%9}, {%0,%1,%2,%3};\n"
        : "+f"(c[0]), "+f"(c[1]), "+f"(c[2]), "+f"(c[3])
        : "r"(a[0]), "r"(a[1]), "r"(a[2]), "r"(a[3]), "r"(b[0]), "r"(b[1]));
}

__device__ __forceinline__ void epi_write(const GP& p, int m, int n, float v,
                                          long long offO, long long offBias) {
    if (m >= p.M || n >= p.N) return;
    long long o = offO + (long long)m * p.sOm + (long long)n * p.sOn;
    float bsv = p.bias ? p.bias[offBias + n] : 0.f;
    switch (p.mode) {
        case 0: p.O[o] = v + bsv; break;
        case 1: { float z = v + bsv; if (p.O2) p.O2[o] = z;
                  float sg = 1.f / (1.f + __expf(-z)); p.O[o] = z * sg; } break;
        case 2: { float z = v + bsv; p.O[o] = 0.5f * z * (1.f + erff(z * 0.70710678118f)); } break;
        case 3: { float z = v * p.scale; if (m >= p.prefix && n > m) z = -1e30f; p.O[o] = z; } break;
        case 4: p.O[o] = p.aux[o] + v + bsv; break;
        case 5: p.O[o] = (v + bsv - p.aux[o]) * p.scale; break;
        case 6: { float z = p.aux[o]; float sg = 1.f / (1.f + __expf(-z));
                  p.O[o] = v * sg * (1.f + z * (1.f - sg)); } break;
        case 7: { float nm = 0.9f * p.aux2[o] + v; p.O2[o] = nm;
                  p.O[o] = 0.999f * p.aux[o] - 0.01f * nm; } break;
    }
}

// ---- tf32 tensor-core GEMM: 128x128 block, k-tile 16, 8 warps, 2-stage double buffer ----
// tf32 conversion happens ONCE at smem store; inner loop is pure LDS + MMA.
__global__ __launch_bounds__(256) void gemm_tc(GP p) {
    __shared__ float As[2][16][132];
    __shared__ float Bs[2][16][132];
    int bz = blockIdx.z;
    int bo = bz / p.binner, bi = bz % p.binner;
    const float* Ap = p.A  + (long long)bo * p.bA + (long long)bi * p.bA2;
    const float* Bp = p.Bm + (long long)bo * p.bB + (long long)bi * p.bB2;
    int m0 = blockIdx.y * 128, n0 = blockIdx.x * 128;
    int tid = threadIdx.x;
    int warp = tid >> 5, lane = tid & 31;
    int wm = warp & 1, wn = warp >> 1;      // warp tile: 64 (m) x 32 (n)
    int lq = lane >> 2, lr = lane & 3;

    float acc[4][4][4];
#pragma unroll
    for (int i = 0; i < 4; i++)
#pragma unroll
        for (int j = 0; j < 4; j++)
#pragma unroll
            for (int r = 0; r < 4; r++) acc[i][j][r] = 0.f;

    const bool aK = (p.sAk == 1);     // A contiguous along k
    const bool bN = (p.sBn == 1);     // B contiguous along n
    float ra[8], rb[8];

    auto loadA = [&](int k0) {
#pragma unroll
        for (int i = 0; i < 8; i++) {
            int lin = tid + i * 256;
            int kk, mm;
            if (aK) { kk = lin & 15; mm = lin >> 4; }
            else    { mm = lin & 127; kk = lin >> 7; }
            int gm = m0 + mm, gk = k0 + kk;
            ra[i] = (gm < p.M && gk < p.K)
                ? Ap[(long long)gm * p.sAm + (long long)gk * p.sAk] : 0.f;
        }
    };
    auto loadB = [&](int k0) {
#pragma unroll
        for (int i = 0; i < 8; i++) {
            int lin = tid + i * 256;
            int kk, nn;
            if (bN) { nn = lin & 127; kk = lin >> 7; }
            else    { kk = lin & 15; nn = lin >> 4; }
            int gn = n0 + nn, gk = k0 + kk;
            rb[i] = (gn < p.N && gk < p.K)
                ? Bp[(long long)gk * p.sBk + (long long)gn * p.sBn] : 0.f;
        }
    };
    auto storeA = [&](int buf) {
#pragma unroll
        for (int i = 0; i < 8; i++) {
            int lin = tid + i * 256;
            int kk, mm;
            if (aK) { kk = lin & 15; mm = lin >> 4; }
            else    { mm = lin & 127; kk = lin >> 7; }
            As[buf][kk][mm] = __uint_as_float(f2tf(ra[i]));
        }
    };
    auto storeB = [&](int buf) {
#pragma unroll
        for (int i = 0; i < 8; i++) {
            int lin = tid + i * 256;
            int kk, nn;
            if (bN) { nn = lin & 127; kk = lin >> 7; }
            else    { kk = lin & 15; nn = lin >> 4; }
            Bs[buf][kk][nn] = __uint_as_float(f2tf(rb[i]));
        }
    };

    int nk = (p.K + 15) >> 4;
    loadA(0); loadB(0);
    storeA(0); storeB(0);

    for (int kt = 0; kt < nk; kt++) {
        int buf = kt & 1;
        __syncthreads();
        if (kt + 1 < nk) { loadA((kt + 1) << 4); loadB((kt + 1) << 4); }

#pragma unroll
        for (int ks = 0; ks < 16; ks += 8) {
            unsigned af[4][4], bf[4][2];
#pragma unroll
            for (int mf = 0; mf < 4; mf++) {
                int cm = wm * 64 + mf * 16 + lq;
                af[mf][0] = __float_as_uint(As[buf][ks + lr][cm]);
                af[mf][1] = __float_as_uint(As[buf][ks + lr][cm + 8]);
                af[mf][2] = __float_as_uint(As[buf][ks + lr + 4][cm]);
                af[mf][3] = __float_as_uint(As[buf][ks + lr + 4][cm + 8]);
            }
#pragma unroll
            for (int nf = 0; nf < 4; nf++) {
                int cn = wn * 32 + nf * 8 + lq;
                bf[nf][0] = __float_as_uint(Bs[buf][ks + lr][cn]);
                bf[nf][1] = __float_as_uint(Bs[buf][ks + lr + 4][cn]);
            }
#pragma unroll
            for (int mf = 0; mf < 4; mf++)
#pragma unroll
                for (int nf = 0; nf < 4; nf++)
                    mma_tf32(acc[mf][nf], af[mf], bf[nf]);
        }

        if (kt + 1 < nk) { storeA(buf ^ 1); storeB(buf ^ 1); }
    }

    long long offO = (long long)bo * p.bO + (long long)bi * p.bO2;
    long long offBias = p.bBias * bz;
#pragma unroll
    for (int mf = 0; mf < 4; mf++) {
        int row = m0 + wm * 64 + mf * 16 + lq;
#pragma unroll
        for (int nf = 0; nf < 4; nf++) {
            int col = n0 + wn * 32 + nf * 8 + lr * 2;
            epi_write(p, row,     col,     acc[mf][nf][0], offO, offBias);
            epi_write(p, row,     col + 1, acc[mf][nf][1], offO, offBias);
            epi_write(p, row + 8, col,     acc[mf][nf][2], offO, offBias);
            epi_write(p, row + 8, col + 1, acc[mf][nf][3], offO, offBias);
        }
    }
}

// ---------------- elementwise / reduction kernels ----------------
__global__ void pool_k(const float* mem, float* pool) {
    int i = blockIdx.x * 256 + threadIdx.x;
    if (i >= Bn * Mn * Cn) return;
    int c = i % Cn;
    int r = i / Cn;
    int m = r % Mn;
    int b = r / Mn;
    const float* pp = mem + ((long long)b * Tn + m * (Tn / Mn)) * Cn + c;
    float s = 0.f;
#pragma unroll 8
    for (int j = 0; j < Tn / Mn; j++) s += pp[(long long)j * Cn];
    pool[i] = s * (1.f / (Tn / Mn));
}

__global__ void build_xa_k(const float* retr, const float* persist, const float* x, float* xa) {
    long long i = (long long)blockIdx.x * 256 + threadIdx.x;
    if (i >= (long long)Bn * TAn * Cn) return;
    int c = (int)(i % Cn);
    long long r = i / Cn;
    int t = (int)(r % TAn);
    int b = (int)(r / TAn);
    float v;
    if (t < Mn)        v = retr[((long long)b * Mn + t) * Cn + c];
    else if (t < PREn) v = persist[(long long)(t - Mn) * Cn + c];
    else               v = x[((long long)b * Tn + (t - PREn)) * Cn + c];
    xa[i] = v;
}

__global__ void ln_k(const float* x, float* o, const float* w, const float* bb) {
    long long row = blockIdx.x;
    const float* xr = x + row * Cn;
    float* orow = o + row * Cn;
    int t = threadIdx.x;
    __shared__ float s1[256], s2[256];
    float v0 = xr[t], v1 = xr[t + 256], v2 = xr[t + 512];
    s1[t] = v0 + v1 + v2;
    s2[t] = v0 * v0 + v1 * v1 + v2 * v2;
    __syncthreads();
    for (int st = 128; st > 0; st >>= 1) {
        if (t < st) { s1[t] += s1[t + st]; s2[t] += s2[t + st]; }
        __syncthreads();
    }
    float mean = s1[0] * (1.f / Cn);
    float var  = s2[0] * (1.f / Cn) - mean * mean;
    float rs = rsqrtf(var + 1e-5f);
    orow[t]       = (v0 - mean) * rs * w[t]       + bb[t];
    orow[t + 256] = (v1 - mean) * rs * w[t + 256] + bb[t + 256];
    orow[t + 512] = (v2 - mean) * rs * w[t + 512] + bb[t + 512];
}

__global__ void softmax_k(float* a) {
    long long row = blockIdx.x;
    float* r = a + row * TAn;
    int t = threadIdx.x;
    __shared__ float red[256];
    float mx = -1e30f;
    for (int c = t; c < TAn; c += 256) mx = fmaxf(mx, r[c]);
    red[t] = mx; __syncthreads();
    for (int st = 128; st > 0; st >>= 1) { if (t < st) red[t] = fmaxf(red[t], red[t + st]); __syncthreads(); }
    mx = red[0]; __syncthreads();
    float s = 0.f;
    for (int c = t; c < TAn; c += 256) { float e = __expf(r[c] - mx); r[c] = e; s += e; }
    red[t] = s; __syncthreads();
    for (int st = 128; st > 0; st >>= 1) { if (t < st) red[t] += red[t + st]; __syncthreads(); }
    float inv = 1.f / red[0];
    for (int c = t; c < TAn; c += 256) r[c] *= inv;
}

__global__ void copyout_k(const float* xa, float* go, float* dout) {
    long long i = (long long)blockIdx.x * 256 + threadIdx.x;
    if (i >= (long long)Bn * Tn * Cn) return;
    int c = (int)(i % Cn);
    long long r = i / Cn;
    int t = (int)(r % Tn);
    int b = (int)(r / Tn);
    float v = xa[((long long)b * TAn + PREn + t) * Cn + c];
    go[i] = v;
    dout[i] = v;
}

__global__ void colsum_part_k(const float* src, float* part, int cols) {
    int i = blockIdx.x * 256 + threadIdx.x;
    int total = SLICES * Bn * cols;
    if (i >= total) return;
    int s = i / (Bn * cols);
    int rem = i % (Bn * cols);
    int b = rem / cols, c = rem % cols;
    const float* p = src + ((long long)b * Tn + s * (Tn / SLICES)) * cols + c;
    float g = 0.f;
    for (int r = 0; r < Tn / SLICES; r++) g += p[(long long)r * cols];
    part[i] = g;
}

__global__ void colsum_fin_k(const float* part, const float* memb, const float* mom,
                             float* nb, float* nm, int n) {
    int i = blockIdx.x * 256 + threadIdx.x;
    if (i >= n) return;
    float g = 0.f;
    for (int s = 0; s < SLICES; s++) g += part[(long long)s * n + i];
    float m2 = 0.9f * mom[i] + g;
    nm[i] = m2;
    nb[i] = 0.999f * memb[i] - 0.01f * m2;
}

// ---------------- host ----------------
static void run_gemm(const float* A, long long sAm, long long sAk, long long bA, long long bA2,
                     const float* Bm, long long sBk, long long sBn, long long bB, long long bB2,
                     float* O, long long sOm, long long sOn, long long bO, long long bO2,
                     int M, int N, int K, int batch, int binner,
                     const float* bias, long long bBias, int mode,
                     float* O2, const float* aux, const float* aux2, float scale)
{
    GP p;
    p.A = A; p.Bm = Bm; p.O = O; p.O2 = O2; p.bias = bias; p.aux = aux; p.aux2 = aux2;
    p.M = M; p.N = N; p.K = K; p.binner = binner;
    p.sAm = sAm; p.sAk = sAk; p.bA = bA; p.bA2 = bA2;
    p.sBk = sBk; p.sBn = sBn; p.bB = bB; p.bB2 = bB2;
    p.sOm = sOm; p.sOn = sOn; p.bO = bO; p.bO2 = bO2;
    p.bBias = bBias; p.mode = mode; p.prefix = PREn; p.scale = scale;
    dim3 g((N + 127) / 128, (M + 127) / 128, batch);
    gemm_tc<<<g, 256>>>(p);
}

extern "C" void kernel_launch(void* const* d_in, const int* in_sizes, int n_in,
                              void* d_out, int out_size) {
    const float* x           = (const float*)d_in[0];
    const float* persist     = (const float*)d_in[1];
    const float* ln1_w       = (const float*)d_in[2];
    const float* ln1_b       = (const float*)d_in[3];
    const float* ln2_w       = (const float*)d_in[4];
    const float* ln2_b       = (const float*)d_in[5];
    const float* attn_w      = (const float*)d_in[6];
    const float* attn_b      = (const float*)d_in[7];
    const float* attn_proj_w = (const float*)d_in[8];
    const float* attn_proj_b = (const float*)d_in[9];
    const float* fc_w        = (const float*)d_in[10];
    const float* fc_b        = (const float*)d_in[11];
    const float* mlp_proj_w  = (const float*)d_in[12];
    const float* mlp_proj_b  = (const float*)d_in[13];
    const float* q_w         = (const float*)d_in[14];
    const float* q_b         = (const float*)d_in[15];
    const float* k_w         = (const float*)d_in[16];
    const float* k_b         = (const float*)d_in[17];
    const float* v_w         = (const float*)d_in[18];
    const float* v_b         = (const float*)d_in[19];
    const float* o_w         = (const float*)d_in[20];
    const float* o_b         = (const float*)d_in[21];
    const float* mem_w0      = (const float*)d_in[22];
    const float* mem_b0      = (const float*)d_in[23];
    const float* mem_w1      = (const float*)d_in[24];
    const float* mem_b1      = (const float*)d_in[25];
    const float* mom_w0      = (const float*)d_in[26];
    const float* mom_b0      = (const float*)d_in[27];
    const float* mom_w1      = (const float*)d_in[28];
    const float* mom_b1      = (const float*)d_in[29];
    float* out = (float*)d_out;

    float *Q, *HB, *MEM, *POOL, *RETR, *XA, *HLN, *QKV, *ATT, *Y, *FC, *OUT, *KEY, *VAL,
          *PRE, *HH, *DPR, *DHH, *P0, *P1;
    cudaGetSymbolAddress((void**)&Q, g_q);
    cudaGetSymbolAddress((void**)&HB, g_hbuf);
    cudaGetSymbolAddress((void**)&MEM, g_mem);
    cudaGetSymbolAddress((void**)&POOL, g_pool);
    cudaGetSymbolAddress((void**)&RETR, g_retr);
    cudaGetSymbolAddress((void**)&XA, g_xa);
    cudaGetSymbolAddress((void**)&HLN, g_hln);
    cudaGetSymbolAddress((void**)&QKV, g_qkv);
    cudaGetSymbolAddress((void**)&ATT, g_att);
    cudaGetSymbolAddress((void**)&Y, g_y);
    cudaGetSymbolAddress((void**)&FC, g_fc);
    cudaGetSymbolAddress((void**)&OUT, g_o);
    cudaGetSymbolAddress((void**)&KEY, g_key);
    cudaGetSymbolAddress((void**)&VAL, g_val);
    cudaGetSymbolAddress((void**)&PRE, g_pre);
    cudaGetSymbolAddress((void**)&HH, g_hh);
    cudaGetSymbolAddress((void**)&DPR, g_dpr);
    cudaGetSymbolAddress((void**)&DHH, g_dhh);
    cudaGetSymbolAddress((void**)&P0, g_p0);
    cudaGetSymbolAddress((void**)&P1, g_p1);

    const long long TC   = (long long)Tn * Cn;
    const long long TH   = (long long)Tn * HIDn;
    const long long CH   = (long long)Cn * HIDn;
    const long long HC   = (long long)HIDn * Cn;
    const long long TAC  = (long long)TAn * Cn;
    const long long TA3C = (long long)TAn * 3 * Cn;
    const long long TATA = (long long)TAn * TAn;

    const long long o_nw0  = 6291456LL;
    const long long o_nb0  = 15728640LL;
    const long long o_nw1  = 15740928LL;
    const long long o_nb1  = 25178112LL;
    const long long o_nmw0 = 25184256LL;
    const long long o_nmb0 = 34621440LL;
    const long long o_nmw1 = 34633728LL;
    const long long o_nmb1 = 44070912LL;

    run_gemm(x, Cn, 1, 0, 0,  q_w, 1, Cn, 0, 0,  Q, Cn, 1, 0, 0,
             Bn * Tn, Cn, Cn, 1, 1, q_b, 0, 0, nullptr, nullptr, nullptr, 0.f);
    run_gemm(Q, Cn, 1, TC, 0,  mem_w0, 1, Cn, HC, 0,  HB, HIDn, 1, TH, 0,
             Tn, HIDn, Cn, Bn, 1, mem_b0, HIDn, 1, nullptr, nullptr, nullptr, 0.f);
    run_gemm(HB, HIDn, 1, TH, 0,  mem_w1, 1, HIDn, CH, 0,  MEM, Cn, 1, TC, 0,
             Tn, Cn, HIDn, Bn, 1, mem_b1, Cn, 0, nullptr, nullptr, nullptr, 0.f);
    pool_k<<<(Bn * Mn * Cn + 255) / 256, 256>>>(MEM, POOL);
    run_gemm(POOL, Cn, 1, 0, 0,  o_w, 1, Cn, 0, 0,  RETR, Cn, 1, 0, 0,
             Bn * Mn, Cn, Cn, 1, 1, o_b, 0, 0, nullptr, nullptr, nullptr, 0.f);
    build_xa_k<<<(int)(((long long)Bn * TAn * Cn + 255) / 256), 256>>>(RETR, persist, x, XA);
    ln_k<<<Bn * TAn, 256>>>(XA, HLN, ln1_w, ln1_b);
    run_gemm(HLN, Cn, 1, 0, 0,  attn_w, 1, Cn, 0, 0,  QKV, 3 * Cn, 1, 0, 0,
             Bn * TAn, 3 * Cn, Cn, 1, 1, attn_b, 0, 0, nullptr, nullptr, nullptr, 0.f);
    run_gemm(QKV, 3 * Cn, 1, TA3C, 64,  QKV + Cn, 1, 3 * Cn, TA3C, 64,
             ATT, TAn, 1, (long long)Hn * TATA, TATA,
             TAn, TAn, 64, Bn * Hn, Hn, nullptr, 0, 3, nullptr, nullptr, nullptr, 0.125f);
    softmax_k<<<Bn * Hn * TAn, 256>>>(ATT);
    run_gemm(ATT, TAn, 1, (long long)Hn * TATA, TATA,  QKV + 2 * Cn, 3 * Cn, 1, TA3C, 64,
             Y, Cn, 1, TAC, 64,
             TAn, 64, TAn, Bn * Hn, Hn, nullptr, 0, 0, nullptr, nullptr, nullptr, 0.f);
    run_gemm(Y, Cn, 1, 0, 0,  attn_proj_w, 1, Cn, 0, 0,  XA, Cn, 1, 0, 0,
             Bn * TAn, Cn, Cn, 1, 1, attn_proj_b, 0, 4, nullptr, XA, nullptr, 0.f);
    ln_k<<<Bn * TAn, 256>>>(XA, HLN, ln2_w, ln2_b);
    run_gemm(HLN, Cn, 1, 0, 0,  fc_w, 1, Cn, 0, 0,  FC, 4 * Cn, 1, 0, 0,
             Bn * TAn, 4 * Cn, Cn, 1, 1, fc_b, 0, 2, nullptr, nullptr, nullptr, 0.f);
    run_gemm(FC, 4 * Cn, 1, 0, 0,  mlp_proj_w, 1, 4 * Cn, 0, 0,  XA, Cn, 1, 0, 0,
             Bn * TAn, Cn, 4 * Cn, 1, 1, mlp_proj_b, 0, 4, nullptr, XA, nullptr, 0.f);
    copyout_k<<<(int)(((long long)Bn * Tn * Cn + 255) / 256), 256>>>(XA, OUT, out);
    run_gemm(OUT, Cn, 1, 0, 0,  k_w, 1, Cn, 0, 0,  KEY, Cn, 1, 0, 0,
             Bn * Tn, Cn, Cn, 1, 1, k_b, 0, 0, nullptr, nullptr, nullptr, 0.f);
    run_gemm(OUT, Cn, 1, 0, 0,  v_w, 1, Cn, 0, 0,  VAL, Cn, 1, 0, 0,
             Bn * Tn, Cn, Cn, 1, 1, v_b, 0, 0, nullptr, nullptr, nullptr, 0.f);
    run_gemm(KEY, Cn, 1, TC, 0,  mem_w0, 1, Cn, HC, 0,  HH, HIDn, 1, TH, 0,
             Tn, HIDn, Cn, Bn, 1, mem_b0, HIDn, 1, PRE, nullptr, nullptr, 0.f);
    run_gemm(HH, HIDn, 1, TH, 0,  mem_w1, 1, HIDn, CH, 0,  DPR, Cn, 1, TC, 0,
             Tn, Cn, HIDn, Bn, 1, mem_b1, Cn, 5, nullptr, VAL, nullptr,
             2.f / (float)(Tn * Cn));
    run_gemm(DPR, 1, Cn, TC, 0,  HH, HIDn, 1, TH, 0,  out + o_nw1, HIDn, 1, CH, 0,
             Cn, HIDn, Tn, Bn, 1, nullptr, 0, 7, out + o_nmw1, mem_w1, mom_w1, 0.f);
    run_gemm(DPR, Cn, 1, TC, 0,  mem_w1, HIDn, 1, CH, 0,  DHH, HIDn, 1, TH, 0,
             Tn, HIDn, Cn, Bn, 1, nullptr, 0, 6, nullptr, PRE, nullptr, 0.f);
    run_gemm(DHH, 1, HIDn, TH, 0,  KEY, Cn, 1, TC, 0,  out + o_nw0, Cn, 1, HC, 0,
             HIDn, Cn, Tn, Bn, 1, nullptr, 0, 7, out + o_nmw0, mem_w0, mom_w0, 0.f);
    colsum_part_k<<<(SLICES * Bn * Cn + 255) / 256, 256>>>(DPR, P1, Cn);
    colsum_fin_k<<<(Bn * Cn + 255) / 256, 256>>>(P1, mem_b1, mom_b1,
                                                 out + o_nb1, out + o_nmb1, Bn * Cn);
    colsum_part_k<<<(SLICES * Bn * HIDn + 255) / 256, 256>>>(DHH, P0, HIDn);
    colsum_fin_k<<<(Bn * HIDn + 255) / 256, 256>>>(P0, mem_b0, mom_b0,
                                                   out + o_nb0, out + o_nmb0, Bn * HIDn);
    (void)in_sizes; (void)n_in; (void)out_size;
}